// round 15
// baseline (speedup 1.0000x reference)
#include <cuda_runtime.h>
#include <cuda_bf16.h>
#include <cstdint>

typedef uint32_t u32;
typedef unsigned long long u64;
#define EPSBN 1e-5f
#define TPB 256
#define TILE_M 64
#define GGRID 64

// ---------------- device globals ----------------
// gF: L1 fused weights A0[3*64]@0, C0@192, C1@256, C2@384, C3@640
#define OFF_A0 0
#define OFF_C0 192
#define OFF_C1 256
#define OFF_C2 384
#define OFF_C3 640
__device__ float gF[704];

// gB: fragment-baked bf16 weight chunks (hi plane then lo plane per chunk)
// L2: NT=16, 2 chunks x 4096 u32 ; L3: NT=32, 4 x 8192 ; L4: NT=8, 8 x 2048
#define GB_L2 0
#define GB_L3 8192
#define GB_L4 40960
__device__ u32 gB[57344];

// ---------------- smem byte offsets ----------------
#define SB_SEG 0
#define SB_X   256
#define SB_A2  1024      // 1024 u64 hi + 1024 u64 lo  (16KB)
#define SB_A3  17408     // 2048 + 2048                (32KB)
#define SB_A4  50176     // 4096 + 4096                (64KB)
#define SB_B   115712    // 3 slots x 32768            (96KB)
#define SB_TOT 214016

// ---------------- helpers ----------------
__device__ __forceinline__ void cpa16(u32 dst, const float* src){
  asm volatile("cp.async.ca.shared.global [%0], [%1], 16;" :: "r"(dst), "l"(src));
}
__device__ __forceinline__ void mma16816(float* c,
    u32 a0,u32 a1,u32 a2,u32 a3, u32 b0,u32 b1){
  asm volatile("mma.sync.aligned.m16n8k16.row.col.f32.bf16.bf16.f32 "
    "{%0,%1,%2,%3}, {%4,%5,%6,%7}, {%8,%9}, {%0,%1,%2,%3};"
    : "+f"(c[0]),"+f"(c[1]),"+f"(c[2]),"+f"(c[3])
    : "r"(a0),"r"(a1),"r"(a2),"r"(a3),"r"(b0),"r"(b1));
}
__device__ __forceinline__ u32 pkbf(float v0, float v1, float& r0, float& r1){
  __nv_bfloat16 h0=__float2bfloat16_rn(v0), h1=__float2bfloat16_rn(v1);
  r0 = v0-__bfloat162float(h0); r1 = v1-__bfloat162float(h1);
  return (u32)__bfloat16_as_ushort(h0) | ((u32)__bfloat16_as_ushort(h1)<<16);
}
__device__ __forceinline__ u32 pkbf2(float v0, float v1){
  __nv_bfloat16 h0=__float2bfloat16_rn(v0), h1=__float2bfloat16_rn(v1);
  return (u32)__bfloat16_as_ushort(h0) | ((u32)__bfloat16_as_ushort(h1)<<16);
}

// ---------------- prep: fold BN, split bf16, bake fragment layout ----------------
__device__ __forceinline__ void bakeB(u32* dst, int NT, int k0, int n, float v0, float v1){
  float r0, r1;
  u32 hw = pkbf(v0, v1, r0, r1);
  u32 lw = pkbf2(r0, r1);
  int kc = k0>>5, kp = (k0>>4)&1, nt = n>>3;
  int ln = (n&7)*4 + ((k0>>1)&3);
  int reg = (k0&15)>>3;
  int cb = kc*NT*256;
  int idx = ((kp*NT+nt)*32+ln)*2 + reg;
  dst[cb+idx] = hw;
  dst[cb+NT*128+idx] = lw;
}

__global__ void prep_kernel(
  const float* __restrict__ bn0_g, const float* __restrict__ bn0_b,
  const float* __restrict__ bn0_m, const float* __restrict__ bn0_v,
  const float* __restrict__ bn1_g, const float* __restrict__ bn1_b,
  const float* __restrict__ bn1_m, const float* __restrict__ bn1_v,
  const float* __restrict__ bn2_g, const float* __restrict__ bn2_b,
  const float* __restrict__ bn2_m, const float* __restrict__ bn2_v,
  const float* __restrict__ bn3_g, const float* __restrict__ bn3_b,
  const float* __restrict__ bn3_m, const float* __restrict__ bn3_v,
  const float* __restrict__ W0, const float* __restrict__ b0,
  const float* __restrict__ W1, const float* __restrict__ b1,
  const float* __restrict__ W2, const float* __restrict__ b2,
  const float* __restrict__ W3, const float* __restrict__ b3)
{
  int e = blockIdx.x*blockDim.x + threadIdx.x;
  if (e < 3*64) {
    int k = e/64, n = e%64;
    float s0 = bn0_g[k]*rsqrtf(bn0_v[k]+EPSBN);
    float s1 = bn1_g[n]*rsqrtf(bn1_v[n]+EPSBN);
    gF[OFF_A0+e] = s0*W0[e]*s1;
  }
  if (e < 64) {
    float s1 = bn1_g[e]*rsqrtf(bn1_v[e]+EPSBN);
    float t1 = bn1_b[e]-bn1_m[e]*s1;
    float acc = b0[e];
    for (int k=0;k<3;k++){
      float s0 = bn0_g[k]*rsqrtf(bn0_v[k]+EPSBN);
      float t0 = bn0_b[k]-bn0_m[k]*s0;
      acc += t0*W0[k*64+e];
    }
    gF[OFF_C0+e] = acc*s1+t1;
  }
  if (e < 128) {
    float s2 = bn2_g[e]*rsqrtf(bn2_v[e]+EPSBN);
    gF[OFF_C1+e] = b1[e]*s2 + bn2_b[e]-bn2_m[e]*s2;
  }
  if (e < 256) {
    float s3 = bn3_g[e]*rsqrtf(bn3_v[e]+EPSBN);
    gF[OFF_C2+e] = b2[e]*s3 + bn3_b[e]-bn3_m[e]*s3;
  }
  if (e < 64) gF[OFF_C3+e] = b3[e];

  if (e < 32*128) {   // L2: k pairs(32) x n(128)
    int kp = e/128, n = e%128; int k0 = kp*2;
    float s2 = bn2_g[n]*rsqrtf(bn2_v[n]+EPSBN);
    bakeB(gB+GB_L2, 16, k0, n, W1[k0*128+n]*s2, W1[(k0+1)*128+n]*s2);
  }
  if (e < 64*256) {   // L3
    int kp = e/256, n = e%256; int k0 = kp*2;
    float s3 = bn3_g[n]*rsqrtf(bn3_v[n]+EPSBN);
    bakeB(gB+GB_L3, 32, k0, n, W2[k0*256+n]*s3, W2[(k0+1)*256+n]*s3);
  }
  if (e < 128*64) {   // L4
    int kp = e/64, n = e%64; int k0 = kp*2;
    bakeB(gB+GB_L4, 8, k0, n, W3[k0*64+n], W3[(k0+1)*64+n]);
  }
}

// ---------------- init / finalize (order-preserving uint encoding) ----------------
__global__ void init_kernel(uint4* __restrict__ out, int n16){
  int i = blockIdx.x*blockDim.x + threadIdx.x;
  if (i < n16) out[i] = make_uint4(0u,0u,0u,0u);
}
__device__ __forceinline__ unsigned dec1(unsigned u){
  if (u == 0u) return 0u;
  return (u & 0x80000000u) ? (u & 0x7FFFFFFFu) : ~u;
}
__global__ void finalize_kernel(uint4* __restrict__ out, int n16){
  int i = blockIdx.x*blockDim.x + threadIdx.x;
  if (i < n16){
    uint4 v = out[i];
    v.x = dec1(v.x); v.y = dec1(v.y); v.z = dec1(v.z); v.w = dec1(v.w);
    out[i] = v;
  }
}
__device__ __forceinline__ void atomicMaxEnc(unsigned* a, float f){
  unsigned b = __float_as_uint(f);
  unsigned u = ((int)b < 0) ? ~b : (b | 0x80000000u);
  atomicMax(a, u);
}

// ---------------- B staging ----------------
template<int NT>
__device__ __forceinline__ void stageB(u32 sbB, int slot, const u32* gBl, int c, int t){
  const float* s = (const float*)(gBl + (size_t)c*NT*256) + t*4;
  u32 d = sbB + (u32)slot*32768u + (u32)t*16u;
  #pragma unroll
  for (int r=0;r<NT/4;r++) cpa16(d + (u32)r*4096u, s + r*1024);
  asm volatile("cp.async.commit_group;" ::: "memory");
}

// ---------------- generic layer ----------------
template<int NT,int NC,int PNT,int NTG>
__device__ __forceinline__ void layer_run(char* smem, u32 sbB,
    const u32* gBl, const float* bias, const u64* aHi, const u64* aLo,
    float (&acc)[2][NTG][4], int t, int lane, int mi, int ng)
{
  #pragma unroll
  for (int m2=0;m2<2;m2++)
    #pragma unroll
    for (int nt=0;nt<NTG;nt++){
      int col0 = (ng*NTG+nt)*8 + (lane&3)*2;
      float b0v = bias[col0], b1v = bias[col0+1];
      acc[m2][nt][0]=b0v; acc[m2][nt][1]=b1v; acc[m2][nt][2]=b0v; acc[m2][nt][3]=b1v;
    }
  stageB<NT>(sbB, 0, gBl, 0, t);
  stageB<NT>(sbB, 1, gBl, 1, t);

  #pragma unroll 1
  for (int c=0;c<NC;c++){
    if (c==NC-1) asm volatile("cp.async.wait_group 0;" ::: "memory");
    else         asm volatile("cp.async.wait_group 1;" ::: "memory");
    __syncthreads();
    if (c+2<NC) stageB<NT>(sbB, (c+2)%3, gBl, c+2, t);
    const u64* bHi = (const u64*)(smem + SB_B + (size_t)(c%3)*32768);
    const u64* bLo = bHi + NT*64;
    #pragma unroll
    for (int kp=0;kp<2;kp++){
      int kt = c*2+kp;
      u64 h01[2], h23[2], l01[2], l23[2];
      #pragma unroll
      for (int m2=0;m2<2;m2++){
        int bidx = ((mi*2+m2)*PNT + 2*kt)*32 + lane;
        h01[m2]=aHi[bidx]; h23[m2]=aHi[bidx+32];
        l01[m2]=aLo[bidx]; l23[m2]=aLo[bidx+32];
      }
      #pragma unroll
      for (int nt=0;nt<NTG;nt++){
        int ntg = ng*NTG+nt;
        u64 bh = bHi[(kp*NT+ntg)*32 + lane];
        u64 bl = bLo[(kp*NT+ntg)*32 + lane];
        u32 bh0=(u32)bh, bh1=(u32)(bh>>32);
        u32 bl0=(u32)bl, bl1=(u32)(bl>>32);
        #pragma unroll
        for (int m2=0;m2<2;m2++){
          u32 A0=(u32)h01[m2], A1=(u32)(h01[m2]>>32);
          u32 A2=(u32)h23[m2], A3=(u32)(h23[m2]>>32);
          u32 L0=(u32)l01[m2], L1=(u32)(l01[m2]>>32);
          u32 L2=(u32)l23[m2], L3=(u32)(l23[m2]>>32);
          mma16816(acc[m2][nt], A0,A1,A2,A3, bh0,bh1);
          mma16816(acc[m2][nt], L0,L1,L2,L3, bh0,bh1);
          mma16816(acc[m2][nt], A0,A1,A2,A3, bl0,bl1);
        }
      }
    }
  }
  __syncthreads();   // all warps done reading B slots / A planes
}

// relu + bf16-split epilogue into next layer's fragment planes
template<int NTG,int PNTN>
__device__ __forceinline__ void epi_split(float (&acc)[2][NTG][4],
    u64* nHi, u64* nLo, int lane, int mi, int ng)
{
  #pragma unroll
  for (int m2=0;m2<2;m2++){
    int mt = mi*2+m2;
    #pragma unroll
    for (int nt=0;nt<NTG;nt++){
      int pn = ng*NTG+nt;
      float v0=fmaxf(acc[m2][nt][0],0.f), v1=fmaxf(acc[m2][nt][1],0.f);
      float v2=fmaxf(acc[m2][nt][2],0.f), v3=fmaxf(acc[m2][nt][3],0.f);
      float r0,r1,r2,r3;
      u32 hw0 = pkbf(v0,v1,r0,r1);
      u32 hw1 = pkbf(v2,v3,r2,r3);
      u32 lw0 = pkbf2(r0,r1);
      u32 lw1 = pkbf2(r2,r3);
      int idx = (mt*PNTN+pn)*32+lane;
      nHi[idx] = (u64)hw0 | ((u64)hw1<<32);
      nLo[idx] = (u64)lw0 | ((u64)lw1<<32);
    }
  }
}

// ---------------- main kernel ----------------
__global__ void __launch_bounds__(TPB,1) mlp_kernel(
    const float* __restrict__ pt_fea, const int* __restrict__ pt_ind,
    unsigned* __restrict__ out, int P, int Nn)
{
  extern __shared__ char smem[];
  u32 sbB = (u32)__cvta_generic_to_shared(smem) + SB_B;
  int t = threadIdx.x, lane = t&31, w = t>>5, mi = w&1, ng = w>>1;
  int base = blockIdx.x*TILE_M;
  int* sSeg = (int*)(smem+SB_SEG);
  float* sX = (float*)(smem+SB_X);

  u64* A2h=(u64*)(smem+SB_A2); u64* A2l=A2h+1024;
  u64* A3h=(u64*)(smem+SB_A3); u64* A3l=A3h+2048;
  u64* A4h=(u64*)(smem+SB_A4); u64* A4l=A4h+4096;

  if (t < TILE_M){
    int p = base + t; float x0=0.f,x1=0.f,x2=0.f; int seg=0;
    if (p < P){
      x0 = pt_fea[p*3]; x1 = pt_fea[p*3+1]; x2 = pt_fea[p*3+2];
      int ix = pt_ind[p*3], iy = pt_ind[p*3+1], iz = pt_ind[p*3+2];
      int bI = p / Nn;
      seg = ((bI*GGRID + iz)*GGRID + iy)*GGRID + ix;
    }
    sX[t*3]=x0; sX[t*3+1]=x1; sX[t*3+2]=x2; sSeg[t]=seg;
  }
  __syncthreads();

  // L1 (K=3) scalar -> A2 fragment records (4 records/thread)
  #pragma unroll
  for (int r=0;r<4;r++){
    int idx = t*4+r;
    int mt = idx>>8, pn = (idx>>5)&7, ln = idx&31;
    int g = ln>>2, tg = ln&3;
    int m0 = mt*16+g, m1 = m0+8;
    int c0 = pn*8 + tg*2;
    float o[4];
    #pragma unroll
    for (int q=0;q<4;q++){
      int m = (q<2)?m0:m1; int c = c0 + (q&1);
      float v = gF[OFF_C0+c] + sX[m*3]*gF[OFF_A0+c]
              + sX[m*3+1]*gF[OFF_A0+64+c] + sX[m*3+2]*gF[OFF_A0+128+c];
      o[q] = fmaxf(v, 0.f);
    }
    float r0,r1,r2,r3;
    u32 hw0 = pkbf(o[0],o[1],r0,r1);
    u32 hw1 = pkbf(o[2],o[3],r2,r3);
    u32 lw0 = pkbf2(r0,r1);
    u32 lw1 = pkbf2(r2,r3);
    int ridx = (mt*8+pn)*32+ln;
    A2h[ridx] = (u64)hw0 | ((u64)hw1<<32);
    A2l[ridx] = (u64)lw0 | ((u64)lw1<<32);
  }

  {  // L2: 64 -> 128
    float acc[2][4][4];
    layer_run<16,2,8,4>(smem, sbB, gB+GB_L2, gF+OFF_C1, A2h, A2l, acc, t, lane, mi, ng);
    epi_split<4,16>(acc, A3h, A3l, lane, mi, ng);
  }
  {  // L3: 128 -> 256
    float acc[2][8][4];
    layer_run<32,4,16,8>(smem, sbB, gB+GB_L3, gF+OFF_C2, A3h, A3l, acc, t, lane, mi, ng);
    epi_split<8,32>(acc, A4h, A4l, lane, mi, ng);
  }
  {  // L4: 256 -> 64, fused scatter-max
    float acc[2][2][4];
    layer_run<8,8,32,2>(smem, sbB, gB+GB_L4, gF+OFF_C3, A4h, A4l, acc, t, lane, mi, ng);
    #pragma unroll
    for (int m2=0;m2<2;m2++){
      int m0 = (mi*2+m2)*16 + (lane>>2), m1 = m0+8;
      int p0 = base+m0, p1 = base+m1;
      #pragma unroll
      for (int nt=0;nt<2;nt++){
        int col0 = (ng*2+nt)*8 + (lane&3)*2;
        if (p0 < P){
          unsigned* d0 = out + (size_t)sSeg[m0]*64 + col0;
          atomicMaxEnc(d0,   acc[m2][nt][0]);
          atomicMaxEnc(d0+1, acc[m2][nt][1]);
        }
        if (p1 < P){
          unsigned* d1 = out + (size_t)sSeg[m1]*64 + col0;
          atomicMaxEnc(d1,   acc[m2][nt][2]);
          atomicMaxEnc(d1+1, acc[m2][nt][3]);
        }
      }
    }
  }
}

// ---------------- launch ----------------
extern "C" void kernel_launch(void* const* d_in, const int* in_sizes, int n_in,
                              void* d_out, int out_size)
{
  const float* pt_fea = (const float*)d_in[0];
  const int*   pt_ind = (const int*)d_in[1];
  const float* a[24];
  for (int i=0;i<24;i++) a[i] = (const float*)d_in[2+i];

  int P  = in_sizes[0] / 3;   // 500000
  int Nn = P / 2;             // points per batch (B=2)

  prep_kernel<<<128, 256>>>(
    a[0],a[1],a[2],a[3], a[4],a[5],a[6],a[7],
    a[8],a[9],a[10],a[11], a[12],a[13],a[14],a[15],
    a[16],a[17], a[18],a[19], a[20],a[21], a[22],a[23]);

  int n16 = out_size / 4;
  init_kernel<<<(n16+255)/256, 256>>>((uint4*)d_out, n16);

  cudaFuncSetAttribute(mlp_kernel, cudaFuncAttributeMaxDynamicSharedMemorySize, SB_TOT);
  int blocks = (P + TILE_M - 1) / TILE_M;
  mlp_kernel<<<blocks, TPB, SB_TOT>>>(pt_fea, pt_ind, (unsigned*)d_out, P, Nn);

  finalize_kernel<<<(n16+255)/256, 256>>>((uint4*)d_out, n16);
}

// round 16
// speedup vs baseline: 1.5065x; 1.5065x over previous
#include <cuda_runtime.h>
#include <cuda_bf16.h>
#include <cstdint>

typedef uint32_t u32;
typedef unsigned long long u64;
#define EPSBN 1e-5f
#define TPB 256
#define TILE_M 64
#define GGRID 64

// ---------------- device globals ----------------
// gF: L1 fused weights A0[3*64]@0, C0@192, C1@256, C2@384, C3@640
#define OFF_A0 0
#define OFF_C0 192
#define OFF_C1 256
#define OFF_C2 384
#define OFF_C3 640
__device__ float gF[704];

// gB: fragment-baked bf16 weight chunks (hi plane then lo plane per chunk)
// L2: NT=16, 2 chunks x 4096 u32 ; L3: NT=32, 4 x 8192 ; L4: NT=8, 8 x 2048
#define GB_L2 0
#define GB_L3 8192
#define GB_L4 40960
__device__ u32 gB[57344];

// ---------------- smem byte offsets ----------------
#define SB_SEG 0
#define SB_X   256
#define SB_A2  1024      // 1024 u64 hi + 1024 u64 lo  (16KB)
#define SB_A3  17408     // 2048 + 2048                (32KB)
#define SB_A4  50176     // 4096 + 4096                (64KB)
#define SB_B   115712    // 3 slots x 32768            (96KB)
#define SB_TOT 214016

// ---------------- helpers ----------------
__device__ __forceinline__ void cpa16(u32 dst, const float* src){
  asm volatile("cp.async.ca.shared.global [%0], [%1], 16;" :: "r"(dst), "l"(src));
}
__device__ __forceinline__ void mma16816(float* c,
    u32 a0,u32 a1,u32 a2,u32 a3, u32 b0,u32 b1){
  asm volatile("mma.sync.aligned.m16n8k16.row.col.f32.bf16.bf16.f32 "
    "{%0,%1,%2,%3}, {%4,%5,%6,%7}, {%8,%9}, {%0,%1,%2,%3};"
    : "+f"(c[0]),"+f"(c[1]),"+f"(c[2]),"+f"(c[3])
    : "r"(a0),"r"(a1),"r"(a2),"r"(a3),"r"(b0),"r"(b1));
}
__device__ __forceinline__ u32 pkbf(float v0, float v1, float& r0, float& r1){
  __nv_bfloat16 h0=__float2bfloat16_rn(v0), h1=__float2bfloat16_rn(v1);
  r0 = v0-__bfloat162float(h0); r1 = v1-__bfloat162float(h1);
  return (u32)__bfloat16_as_ushort(h0) | ((u32)__bfloat16_as_ushort(h1)<<16);
}
__device__ __forceinline__ u32 pkbf2(float v0, float v1){
  __nv_bfloat16 h0=__float2bfloat16_rn(v0), h1=__float2bfloat16_rn(v1);
  return (u32)__bfloat16_as_ushort(h0) | ((u32)__bfloat16_as_ushort(h1)<<16);
}

// ---------------- prep: fold BN, split bf16, bake fragment layout ----------------
__device__ __forceinline__ void bakeB(u32* dst, int NT, int k0, int n, float v0, float v1){
  float r0, r1;
  u32 hw = pkbf(v0, v1, r0, r1);
  u32 lw = pkbf2(r0, r1);
  int kc = k0>>5, kp = (k0>>4)&1, nt = n>>3;
  int ln = (n&7)*4 + ((k0>>1)&3);
  int reg = (k0&15)>>3;
  int cb = kc*NT*256;
  int idx = ((kp*NT+nt)*32+ln)*2 + reg;
  dst[cb+idx] = hw;
  dst[cb+NT*128+idx] = lw;
}

__global__ void prep_kernel(
  const float* __restrict__ bn0_g, const float* __restrict__ bn0_b,
  const float* __restrict__ bn0_m, const float* __restrict__ bn0_v,
  const float* __restrict__ bn1_g, const float* __restrict__ bn1_b,
  const float* __restrict__ bn1_m, const float* __restrict__ bn1_v,
  const float* __restrict__ bn2_g, const float* __restrict__ bn2_b,
  const float* __restrict__ bn2_m, const float* __restrict__ bn2_v,
  const float* __restrict__ bn3_g, const float* __restrict__ bn3_b,
  const float* __restrict__ bn3_m, const float* __restrict__ bn3_v,
  const float* __restrict__ W0, const float* __restrict__ b0,
  const float* __restrict__ W1, const float* __restrict__ b1,
  const float* __restrict__ W2, const float* __restrict__ b2,
  const float* __restrict__ W3, const float* __restrict__ b3)
{
  int e = blockIdx.x*blockDim.x + threadIdx.x;
  if (e < 3*64) {
    int k = e/64, n = e%64;
    float s0 = bn0_g[k]*rsqrtf(bn0_v[k]+EPSBN);
    float s1 = bn1_g[n]*rsqrtf(bn1_v[n]+EPSBN);
    gF[OFF_A0+e] = s0*W0[e]*s1;
  }
  if (e < 64) {
    float s1 = bn1_g[e]*rsqrtf(bn1_v[e]+EPSBN);
    float t1 = bn1_b[e]-bn1_m[e]*s1;
    float acc = b0[e];
    for (int k=0;k<3;k++){
      float s0 = bn0_g[k]*rsqrtf(bn0_v[k]+EPSBN);
      float t0 = bn0_b[k]-bn0_m[k]*s0;
      acc += t0*W0[k*64+e];
    }
    gF[OFF_C0+e] = acc*s1+t1;
  }
  if (e < 128) {
    float s2 = bn2_g[e]*rsqrtf(bn2_v[e]+EPSBN);
    gF[OFF_C1+e] = b1[e]*s2 + bn2_b[e]-bn2_m[e]*s2;
  }
  if (e < 256) {
    float s3 = bn3_g[e]*rsqrtf(bn3_v[e]+EPSBN);
    gF[OFF_C2+e] = b2[e]*s3 + bn3_b[e]-bn3_m[e]*s3;
  }
  if (e < 64) gF[OFF_C3+e] = b3[e];

  if (e < 32*128) {   // L2: k pairs(32) x n(128)
    int kp = e/128, n = e%128; int k0 = kp*2;
    float s2 = bn2_g[n]*rsqrtf(bn2_v[n]+EPSBN);
    bakeB(gB+GB_L2, 16, k0, n, W1[k0*128+n]*s2, W1[(k0+1)*128+n]*s2);
  }
  if (e < 64*256) {   // L3
    int kp = e/256, n = e%256; int k0 = kp*2;
    float s3 = bn3_g[n]*rsqrtf(bn3_v[n]+EPSBN);
    bakeB(gB+GB_L3, 32, k0, n, W2[k0*256+n]*s3, W2[(k0+1)*256+n]*s3);
  }
  if (e < 128*64) {   // L4
    int kp = e/64, n = e%64; int k0 = kp*2;
    bakeB(gB+GB_L4, 8, k0, n, W3[k0*64+n], W3[(k0+1)*64+n]);
  }
}

// ---------------- init / finalize (order-preserving uint encoding) ----------------
__global__ void init_kernel(uint4* __restrict__ out, int n16){
  int i = blockIdx.x*blockDim.x + threadIdx.x;
  if (i < n16) out[i] = make_uint4(0u,0u,0u,0u);
}
__device__ __forceinline__ unsigned dec1(unsigned u){
  if (u == 0u) return 0u;
  return (u & 0x80000000u) ? (u & 0x7FFFFFFFu) : ~u;
}
__global__ void finalize_kernel(uint4* __restrict__ out, int n16){
  int i = blockIdx.x*blockDim.x + threadIdx.x;
  if (i < n16){
    uint4 v = out[i];
    v.x = dec1(v.x); v.y = dec1(v.y); v.z = dec1(v.z); v.w = dec1(v.w);
    out[i] = v;
  }
}
__device__ __forceinline__ void atomicMaxEnc(unsigned* a, float f){
  unsigned b = __float_as_uint(f);
  unsigned u = ((int)b < 0) ? ~b : (b | 0x80000000u);
  atomicMax(a, u);
}

// ---------------- B staging ----------------
template<int NT>
__device__ __forceinline__ void stageB(u32 sbB, int slot, const u32* gBl, int c, int t){
  const float* s = (const float*)(gBl + (size_t)c*NT*256) + t*4;
  u32 d = sbB + (u32)slot*32768u + (u32)t*16u;
  #pragma unroll
  for (int r=0;r<NT/4;r++) cpa16(d + (u32)r*4096u, s + r*1024);
  asm volatile("cp.async.commit_group;" ::: "memory");
}

// ---------------- generic layer ----------------
template<int NT,int NC,int PNT,int NTG>
__device__ __forceinline__ void layer_run(char* smem, u32 sbB,
    const u32* gBl, const float* bias, const u64* aHi, const u64* aLo,
    float (&acc)[2][NTG][4], int t, int lane, int mi, int ng)
{
  #pragma unroll
  for (int m2=0;m2<2;m2++)
    #pragma unroll
    for (int nt=0;nt<NTG;nt++){
      int col0 = (ng*NTG+nt)*8 + (lane&3)*2;
      float b0v = bias[col0], b1v = bias[col0+1];
      acc[m2][nt][0]=b0v; acc[m2][nt][1]=b1v; acc[m2][nt][2]=b0v; acc[m2][nt][3]=b1v;
    }
  stageB<NT>(sbB, 0, gBl, 0, t);
  stageB<NT>(sbB, 1, gBl, 1, t);

  #pragma unroll 1
  for (int c=0;c<NC;c++){
    if (c==NC-1) asm volatile("cp.async.wait_group 0;" ::: "memory");
    else         asm volatile("cp.async.wait_group 1;" ::: "memory");
    __syncthreads();
    if (c+2<NC) stageB<NT>(sbB, (c+2)%3, gBl, c+2, t);
    const u64* bHi = (const u64*)(smem + SB_B + (size_t)(c%3)*32768);
    const u64* bLo = bHi + NT*64;
    #pragma unroll
    for (int kp=0;kp<2;kp++){
      int kt = c*2+kp;
      u64 h01[2], h23[2], l01[2], l23[2];
      #pragma unroll
      for (int m2=0;m2<2;m2++){
        int bidx = ((mi*2+m2)*PNT + 2*kt)*32 + lane;
        h01[m2]=aHi[bidx]; h23[m2]=aHi[bidx+32];
        l01[m2]=aLo[bidx]; l23[m2]=aLo[bidx+32];
      }
      #pragma unroll
      for (int nt=0;nt<NTG;nt++){
        int ntg = ng*NTG+nt;
        u64 bh = bHi[(kp*NT+ntg)*32 + lane];
        u64 bl = bLo[(kp*NT+ntg)*32 + lane];
        u32 bh0=(u32)bh, bh1=(u32)(bh>>32);
        u32 bl0=(u32)bl, bl1=(u32)(bl>>32);
        #pragma unroll
        for (int m2=0;m2<2;m2++){
          u32 A0=(u32)h01[m2], A1=(u32)(h01[m2]>>32);
          u32 A2=(u32)h23[m2], A3=(u32)(h23[m2]>>32);
          u32 L0=(u32)l01[m2], L1=(u32)(l01[m2]>>32);
          u32 L2=(u32)l23[m2], L3=(u32)(l23[m2]>>32);
          mma16816(acc[m2][nt], A0,A1,A2,A3, bh0,bh1);
          mma16816(acc[m2][nt], L0,L1,L2,L3, bh0,bh1);
          mma16816(acc[m2][nt], A0,A1,A2,A3, bl0,bl1);
        }
      }
    }
  }
  __syncthreads();   // all warps done reading B slots / A planes
}

// relu + bf16-split epilogue into next layer's fragment planes
template<int NTG,int PNTN>
__device__ __forceinline__ void epi_split(float (&acc)[2][NTG][4],
    u64* nHi, u64* nLo, int lane, int mi, int ng)
{
  #pragma unroll
  for (int m2=0;m2<2;m2++){
    int mt = mi*2+m2;
    #pragma unroll
    for (int nt=0;nt<NTG;nt++){
      int pn = ng*NTG+nt;
      float v0=fmaxf(acc[m2][nt][0],0.f), v1=fmaxf(acc[m2][nt][1],0.f);
      float v2=fmaxf(acc[m2][nt][2],0.f), v3=fmaxf(acc[m2][nt][3],0.f);
      float r0,r1,r2,r3;
      u32 hw0 = pkbf(v0,v1,r0,r1);
      u32 hw1 = pkbf(v2,v3,r2,r3);
      u32 lw0 = pkbf2(r0,r1);
      u32 lw1 = pkbf2(r2,r3);
      int idx = (mt*PNTN+pn)*32+lane;
      nHi[idx] = (u64)hw0 | ((u64)hw1<<32);
      nLo[idx] = (u64)lw0 | ((u64)lw1<<32);
    }
  }
}

// ---------------- main kernel ----------------
__global__ void __launch_bounds__(TPB,1) mlp_kernel(
    const float* __restrict__ pt_fea, const int* __restrict__ pt_ind,
    unsigned* __restrict__ out, int P, int Nn)
{
  extern __shared__ char smem[];
  u32 sbB = (u32)__cvta_generic_to_shared(smem) + SB_B;
  int t = threadIdx.x, lane = t&31, w = t>>5, mi = w&1, ng = w>>1;
  int base = blockIdx.x*TILE_M;
  int* sSeg = (int*)(smem+SB_SEG);
  float* sX = (float*)(smem+SB_X);

  u64* A2h=(u64*)(smem+SB_A2); u64* A2l=A2h+1024;
  u64* A3h=(u64*)(smem+SB_A3); u64* A3l=A3h+2048;
  u64* A4h=(u64*)(smem+SB_A4); u64* A4l=A4h+4096;

  if (t < TILE_M){
    int p = base + t; float x0=0.f,x1=0.f,x2=0.f; int seg=0;
    if (p < P){
      x0 = pt_fea[p*3]; x1 = pt_fea[p*3+1]; x2 = pt_fea[p*3+2];
      int ix = pt_ind[p*3], iy = pt_ind[p*3+1], iz = pt_ind[p*3+2];
      int bI = p / Nn;
      seg = ((bI*GGRID + iz)*GGRID + iy)*GGRID + ix;
    }
    sX[t*3]=x0; sX[t*3+1]=x1; sX[t*3+2]=x2; sSeg[t]=seg;
  }
  __syncthreads();

  // L1 (K=3) scalar -> A2 fragment records (4 records/thread)
  #pragma unroll
  for (int r=0;r<4;r++){
    int idx = t*4+r;
    int mt = idx>>8, pn = (idx>>5)&7, ln = idx&31;
    int g = ln>>2, tg = ln&3;
    int m0 = mt*16+g, m1 = m0+8;
    int c0 = pn*8 + tg*2;
    float o[4];
    #pragma unroll
    for (int q=0;q<4;q++){
      int m = (q<2)?m0:m1; int c = c0 + (q&1);
      float v = gF[OFF_C0+c] + sX[m*3]*gF[OFF_A0+c]
              + sX[m*3+1]*gF[OFF_A0+64+c] + sX[m*3+2]*gF[OFF_A0+128+c];
      o[q] = fmaxf(v, 0.f);
    }
    float r0,r1,r2,r3;
    u32 hw0 = pkbf(o[0],o[1],r0,r1);
    u32 hw1 = pkbf(o[2],o[3],r2,r3);
    u32 lw0 = pkbf2(r0,r1);
    u32 lw1 = pkbf2(r2,r3);
    int ridx = (mt*8+pn)*32+ln;
    A2h[ridx] = (u64)hw0 | ((u64)hw1<<32);
    A2l[ridx] = (u64)lw0 | ((u64)lw1<<32);
  }

  {  // L2: 64 -> 128
    float acc[2][4][4];
    layer_run<16,2,8,4>(smem, sbB, gB+GB_L2, gF+OFF_C1, A2h, A2l, acc, t, lane, mi, ng);
    epi_split<4,16>(acc, A3h, A3l, lane, mi, ng);
  }
  {  // L3: 128 -> 256
    float acc[2][8][4];
    layer_run<32,4,16,8>(smem, sbB, gB+GB_L3, gF+OFF_C2, A3h, A3l, acc, t, lane, mi, ng);
    epi_split<8,32>(acc, A4h, A4l, lane, mi, ng);
  }
  {  // L4: 256 -> 64, fused scatter-max
    float acc[2][2][4];
    layer_run<8,8,32,2>(smem, sbB, gB+GB_L4, gF+OFF_C3, A4h, A4l, acc, t, lane, mi, ng);
    #pragma unroll
    for (int m2=0;m2<2;m2++){
      int m0 = (mi*2+m2)*16 + (lane>>2), m1 = m0+8;
      int p0 = base+m0, p1 = base+m1;
      #pragma unroll
      for (int nt=0;nt<2;nt++){
        int col0 = (ng*2+nt)*8 + (lane&3)*2;
        if (p0 < P){
          unsigned* d0 = out + (size_t)sSeg[m0]*64 + col0;
          atomicMaxEnc(d0,   acc[m2][nt][0]);
          atomicMaxEnc(d0+1, acc[m2][nt][1]);
        }
        if (p1 < P){
          unsigned* d1 = out + (size_t)sSeg[m1]*64 + col0;
          atomicMaxEnc(d1,   acc[m2][nt][2]);
          atomicMaxEnc(d1+1, acc[m2][nt][3]);
        }
      }
    }
  }
}

// ---------------- launch ----------------
extern "C" void kernel_launch(void* const* d_in, const int* in_sizes, int n_in,
                              void* d_out, int out_size)
{
  const float* pt_fea = (const float*)d_in[0];
  const int*   pt_ind = (const int*)d_in[1];
  const float* a[24];
  for (int i=0;i<24;i++) a[i] = (const float*)d_in[2+i];

  int P  = in_sizes[0] / 3;   // 500000
  int Nn = P / 2;             // points per batch (B=2)

  prep_kernel<<<128, 256>>>(
    a[0],a[1],a[2],a[3], a[4],a[5],a[6],a[7],
    a[8],a[9],a[10],a[11], a[12],a[13],a[14],a[15],
    a[16],a[17], a[18],a[19], a[20],a[21], a[22],a[23]);

  int n16 = out_size / 4;
  init_kernel<<<(n16+255)/256, 256>>>((uint4*)d_out, n16);

  cudaFuncSetAttribute(mlp_kernel, cudaFuncAttributeMaxDynamicSharedMemorySize, SB_TOT);
  int blocks = (P + TILE_M - 1) / TILE_M;
  mlp_kernel<<<blocks, TPB, SB_TOT>>>(pt_fea, pt_ind, (unsigned*)d_out, P, Nn);

  finalize_kernel<<<(n16+255)/256, 256>>>((uint4*)d_out, n16);
}